// round 16
// baseline (speedup 1.0000x reference)
#include <cuda_runtime.h>
#include <cstdint>

// Problem constants
#define T_STEPS 1024
#define BATCH   16
#define NHEADS  12
#define HD      64
#define NG      4
#define NCELLS  (BATCH * NHEADS)          // 192
#define CELLSTR (HD * NG)                 // 256 floats per (t,b,n)
#define TSTRIDE (NCELLS * CELLSTR)        // 49152 floats per timestep of Wx
#define OROW    ((size_t)NCELLS * HD)     // 12288 floats per timestep of out
#define PF      4                         // Wx prefetch distance (timesteps)
#define HPAD    72                        // h replica row stride (bank-spread + 16B aligned)

typedef unsigned long long ull;

__device__ __forceinline__ ull pk2(float lo, float hi) {
    ull r;
    asm("mov.b64 %0, {%1, %2};" : "=l"(r) : "r"(__float_as_uint(lo)), "r"(__float_as_uint(hi)));
    return r;
}
__device__ __forceinline__ void upk2(ull v, float& lo, float& hi) {
    unsigned a, b2;
    asm("mov.b64 {%0, %1}, %2;" : "=r"(a), "=r"(b2) : "l"(v));
    lo = __uint_as_float(a);
    hi = __uint_as_float(b2);
}
__device__ __forceinline__ void ffma2(ull& acc, ull a, ull b) {
    asm("fma.rn.f32x2 %0, %1, %2, %0;" : "+l"(acc) : "l"(a), "l"(b));
}
__device__ __forceinline__ ull fadd2(ull a, ull b) {
    ull r;
    asm("add.rn.f32x2 %0, %1, %2;" : "=l"(r) : "l"(a), "l"(b));
    return r;
}
__device__ __forceinline__ ull fmul2(ull a, ull b) {
    ull r;
    asm("mul.rn.f32x2 %0, %1, %2;" : "=l"(r) : "l"(a), "l"(b));
    return r;
}
__device__ __forceinline__ float frcp(float x) {
    float r;
    asm("rcp.approx.f32 %0, %1;" : "=f"(r) : "f"(x));
    return r;
}
__device__ __forceinline__ float fex2(float x) {
    float r;
    asm("ex2.approx.f32 %0, %1;" : "=f"(r) : "f"(x));
    return r;
}

// Scales folded into R/bias so the activation core is gate-uniform:
//   r = rcp(1 + ex2(s));  a = fma(k, r, m)
//   sigmoid (g in {0,1,3}): s = -log2(e)*x   -> a = r        (k=1,  m=0)
//   tanh    (g == 2):       s = 2*log2(e)*x  -> a = 1 - 2r   (k=-2, m=1)
#define L2E 1.4426950408889634f

__global__ void __launch_bounds__(128, 2)
flashrnn_lstm_kernel(const float* __restrict__ Wx,
                     const float* __restrict__ S0,
                     const float* __restrict__ R,
                     const float* __restrict__ bias,
                     float* __restrict__ out)
{
    const int cell = blockIdx.x;          // 0..191
    const int n = cell % NHEADS;
    const int b = cell / NHEADS;
    const int tid  = threadIdx.x;         // 0..127
    const int warp = tid >> 5;            // 0..3
    const int lane = tid & 31;
    const int g    = lane >> 3;           // gate 0..3 (i,f,z,o)
    const int ob   = lane & 7;            // output sub-index within gate group
    const int oA   = (warp << 3) | ob;    // first owned output (0..31)
    const int oB   = oA + 32;             // second owned output (32..63)

    // Source lanes for shfl.idx gate gather: gate q of output ob lives in lane (q<<3)|ob
    const int Li = ob;        // gate i
    const int Lf = ob | 8;    // gate f
    const int Lz = ob | 16;   // gate z
    const int Lo = ob | 24;   // gate o

    // Gate-replicated ping-pong hidden state: every gate group g keeps a full,
    // bit-identical copy of h. All lanes write UNCONDITIONALLY (no divergent
    // branch -> no BSSY/BSYNC); gate-g lanes across the 4 warps cover all 64
    // outputs. HPAD=72 -> gate bank bases 0/8/16/24: conflict-free STS & LDS.128.
    __shared__ __align__(16) float sh_hrep[2][NG][HPAD];

    // Per-gate activation constants (branch-free core)
    const float sg = (g == 2) ? (2.0f * L2E) : (-L2E);
    const float kg = (g == 2) ? -2.0f : 1.0f;
    const float mg = (g == 2) ?  1.0f : 0.0f;

    // ---- R rows for both slots, pre-scaled by sg, packed f32x2 ----
    // RpA[m]/RpB[m] multiply h elements (2m, 2m+1).
    ull RpA[32], RpB[32];
    {
        const ull sg2 = pk2(sg, sg);
        const float4* rA = reinterpret_cast<const float4*>(
            R + (((size_t)n * NG + g) * HD + oA) * HD);
        const float4* rB = reinterpret_cast<const float4*>(
            R + (((size_t)n * NG + g) * HD + oB) * HD);
#pragma unroll
        for (int k = 0; k < 16; ++k) {
            float4 vA = rA[k];
            float4 vB = rB[k];
            RpA[2 * k]     = fmul2(pk2(vA.x, vA.y), sg2);
            RpA[2 * k + 1] = fmul2(pk2(vA.z, vA.w), sg2);
            RpB[2 * k]     = fmul2(pk2(vB.x, vB.y), sg2);
            RpB[2 * k + 1] = fmul2(pk2(vB.z, vB.w), sg2);
        }
    }
    const float bvsA = bias[((size_t)n * NG + g) * HD + oA] * sg;
    const float bvsB = bias[((size_t)n * NG + g) * HD + oB] * sg;

    // ---- Initial states (c replicated x4 over g-lanes per output) ----
    const size_t bn = (size_t)b * NHEADS + n;
    const float h0A = S0[bn * HD + oA];
    const float h0B = S0[bn * HD + oB];
    float cA = S0[(size_t)NCELLS * HD + bn * HD + oA];
    float cB = S0[(size_t)NCELLS * HD + bn * HD + oB];

    float* out_h = out;                                 // [1025][192][64]
    float* out_c = out + (size_t)(T_STEPS + 1) * OROW;  // second state plane

    // Unconditional output role per lane: g0 -> h[oA], g1 -> c[oA],
    // g2 -> h[oB], g3 -> c[oB]. Exact coverage of both planes.
    const bool gb0 = (g & 1);
    const bool gb1 = (g & 2);
    float* optr = (gb0 ? out_c : out_h) + bn * HD + oA + (gb1 ? 32 : 0);

    // init replicas + t=0 outputs (all unconditional)
    sh_hrep[0][g][oA] = h0A;
    sh_hrep[0][g][oB] = h0B;
    *optr = gb0 ? (gb1 ? cB : cA) : (gb1 ? h0B : h0A);
    optr += OROW;   // -> t=1 row

    // ---- Wx stream pointers (slot B is +32*NG floats from slot A) ----
    const float* wxA = Wx + bn * CELLSTR + (size_t)oA * NG + g;

    __syncthreads();

    float xcA[PF], xcB[PF];
#pragma unroll
    for (int j = 0; j < PF; ++j) {
        xcA[j] = __ldcs(wxA + (size_t)j * TSTRIDE);
        xcB[j] = __ldcs(wxA + (size_t)j * TSTRIDE + 32 * NG);
    }

    int buf = 0;

    // One recurrence step — identical math to the 401us champion; all stores
    // unconditional (no divergent branches in the loop body).
#define STEP_BODY(XA, XB)                                                      \
    {                                                                          \
        const float xbA = fmaf((XA), sg, bvsA);                                \
        const float xbB = fmaf((XB), sg, bvsB);                                \
        ull accA[4], accB[4];                                                  \
        accA[0] = pk2(xbA, 0.0f);                                              \
        accB[0] = pk2(xbB, 0.0f);                                              \
        accA[1] = 0ULL; accA[2] = 0ULL; accA[3] = 0ULL;                        \
        accB[1] = 0ULL; accB[2] = 0ULL; accB[3] = 0ULL;                        \
        const ulonglong2* hb =                                                 \
            reinterpret_cast<const ulonglong2*>(sh_hrep[buf][g]);              \
        _Pragma("unroll")                                                      \
        for (int k = 0; k < 16; ++k) {                                         \
            ulonglong2 t2 = hb[k];                                             \
            ffma2(accA[(2 * k) & 3],     RpA[2 * k],     t2.x);                \
            ffma2(accA[(2 * k + 1) & 3], RpA[2 * k + 1], t2.y);                \
            ffma2(accB[(2 * k) & 3],     RpB[2 * k],     t2.x);                \
            ffma2(accB[(2 * k + 1) & 3], RpB[2 * k + 1], t2.y);                \
        }                                                                      \
        ull sa = fadd2(fadd2(accA[0], accA[1]), fadd2(accA[2], accA[3]));      \
        ull sb = fadd2(fadd2(accB[0], accB[1]), fadd2(accB[2], accB[3]));      \
        float lo, hi;                                                          \
        upk2(sa, lo, hi); const float sA = lo + hi;                            \
        upk2(sb, lo, hi); const float sB = lo + hi;                            \
        const float aA = fmaf(kg, frcp(1.0f + fex2(sA)), mg);                  \
        const float aB = fmaf(kg, frcp(1.0f + fex2(sB)), mg);                  \
        /* gate gather: direct indexed shuffles, no select network */          \
        const float giA = __shfl_sync(0xffffffffu, aA, Li);                    \
        const float gzA = __shfl_sync(0xffffffffu, aA, Lz);                    \
        const float gfA = __shfl_sync(0xffffffffu, aA, Lf);                    \
        const float goA = __shfl_sync(0xffffffffu, aA, Lo);                    \
        const float giB = __shfl_sync(0xffffffffu, aB, Li);                    \
        const float gzB = __shfl_sync(0xffffffffu, aB, Lz);                    \
        const float gfB = __shfl_sync(0xffffffffu, aB, Lf);                    \
        const float goB = __shfl_sync(0xffffffffu, aB, Lo);                    \
        cA = fmaf(gfA, cA, giA * gzA);                                         \
        cB = fmaf(gfB, cB, giB * gzB);                                         \
        const float rA2 = frcp(1.0f + fex2(cA * (2.0f * L2E)));                \
        const float rB2 = frcp(1.0f + fex2(cB * (2.0f * L2E)));                \
        const float hA = fmaf(-(goA + goA), rA2, goA);   /* goA*tanh(cA) */    \
        const float hB = fmaf(-(goB + goB), rB2, goB);                         \
        /* unconditional replica STS (own gate's copy) */                      \
        sh_hrep[buf ^ 1][g][oA] = hA;                                          \
        sh_hrep[buf ^ 1][g][oB] = hB;                                          \
        /* unconditional single STG: per-lane role (h/c, A/B) */               \
        *optr = gb0 ? (gb1 ? cB : cA) : (gb1 ? hB : hA);                       \
        __syncthreads();                                                       \
        buf ^= 1;                                                              \
        optr += OROW;                                                          \
    }

    // ---- main loop: prefetch unconditional (no predication/selects) ----
    for (int t0 = 0; t0 < T_STEPS - PF; t0 += PF) {
        float xnA[PF], xnB[PF];
#pragma unroll
        for (int j = 0; j < PF; ++j) {
            const float* p = wxA + (size_t)(t0 + PF + j) * TSTRIDE;
            xnA[j] = __ldcs(p);
            xnB[j] = __ldcs(p + 32 * NG);
        }
#pragma unroll
        for (int j = 0; j < PF; ++j)
            STEP_BODY(xcA[j], xcB[j])
#pragma unroll
        for (int j = 0; j < PF; ++j) { xcA[j] = xnA[j]; xcB[j] = xnB[j]; }
    }
    // ---- tail: last PF steps, no prefetch ----
#pragma unroll
    for (int j = 0; j < PF; ++j)
        STEP_BODY(xcA[j], xcB[j])

#undef STEP_BODY
}

extern "C" void kernel_launch(void* const* d_in, const int* in_sizes, int n_in,
                              void* d_out, int out_size)
{
    const float* Wx   = (const float*)d_in[0];  // [1024,16,12,64,4]
    const float* S0   = (const float*)d_in[1];  // [2,16,12,64]
    const float* R    = (const float*)d_in[2];  // [12,4,64,64]
    const float* bias = (const float*)d_in[3];  // [12,4,64]
    float* out = (float*)d_out;                 // [2,1025,16,12,64]

    flashrnn_lstm_kernel<<<NCELLS, 128>>>(Wx, S0, R, bias, out);
}

// round 17
// speedup vs baseline: 1.4028x; 1.4028x over previous
#include <cuda_runtime.h>
#include <cstdint>

// Problem constants
#define T_STEPS 1024
#define BATCH   16
#define NHEADS  12
#define HD      64
#define NG      4
#define NCELLS  (BATCH * NHEADS)          // 192
#define CELLSTR (HD * NG)                 // 256 floats per (t,b,n)
#define TSTRIDE (NCELLS * CELLSTR)        // 49152 floats per timestep of Wx
#define OROW    ((size_t)NCELLS * HD)     // 12288 floats per timestep of out
#define PF      8                         // Wx prefetch distance (timesteps)

typedef unsigned long long ull;

__device__ __forceinline__ ull pk2(float lo, float hi) {
    ull r;
    asm("mov.b64 %0, {%1, %2};" : "=l"(r) : "r"(__float_as_uint(lo)), "r"(__float_as_uint(hi)));
    return r;
}
__device__ __forceinline__ void upk2(ull v, float& lo, float& hi) {
    unsigned a, b2;
    asm("mov.b64 {%0, %1}, %2;" : "=r"(a), "=r"(b2) : "l"(v));
    lo = __uint_as_float(a);
    hi = __uint_as_float(b2);
}
__device__ __forceinline__ void ffma2(ull& acc, ull a, ull b) {
    asm("fma.rn.f32x2 %0, %1, %2, %0;" : "+l"(acc) : "l"(a), "l"(b));
}
__device__ __forceinline__ ull fadd2(ull a, ull b) {
    ull r;
    asm("add.rn.f32x2 %0, %1, %2;" : "=l"(r) : "l"(a), "l"(b));
    return r;
}
__device__ __forceinline__ ull fmul2(ull a, ull b) {
    ull r;
    asm("mul.rn.f32x2 %0, %1, %2;" : "=l"(r) : "l"(a), "l"(b));
    return r;
}
__device__ __forceinline__ float frcp(float x) {
    float r;
    asm("rcp.approx.f32 %0, %1;" : "=f"(r) : "f"(x));
    return r;
}
__device__ __forceinline__ float fex2(float x) {
    float r;
    asm("ex2.approx.f32 %0, %1;" : "=f"(r) : "f"(x));
    return r;
}

// Scales folded into R/bias so the activation core is gate-uniform:
//   r = rcp(1 + ex2(s));  a = fma(k, r, m)
//   sigmoid (g in {0,1,3}): s = -log2(e)*x   -> a = r        (k=1,  m=0)
//   tanh    (g == 2):       s = 2*log2(e)*x  -> a = 1 - 2r   (k=-2, m=1)
#define L2E 1.4426950408889634f

__global__ void __launch_bounds__(128, 2)
flashrnn_lstm_kernel(const float* __restrict__ Wx,
                     const float* __restrict__ S0,
                     const float* __restrict__ R,
                     const float* __restrict__ bias,
                     float* __restrict__ out)
{
    const int cell = blockIdx.x;          // 0..191
    const int n = cell % NHEADS;
    const int b = cell / NHEADS;
    const int tid  = threadIdx.x;         // 0..127
    const int warp = tid >> 5;            // 0..3
    const int lane = tid & 31;
    const int g    = lane >> 3;           // gate 0..3 (i,f,z,o)
    const int ob   = lane & 7;            // output sub-index within gate group
    const int oA   = (warp << 3) | ob;    // first owned output (0..31)
    const int oB   = oA + 32;             // second owned output (32..63)

    // Source lanes for shfl.idx gate gather: gate q of output ob lives in lane (q<<3)|ob
    const int Li = ob;        // gate i
    const int Lf = ob | 8;    // gate f
    const int Lz = ob | 16;   // gate z
    const int Lo = ob | 24;   // gate o

    __shared__ __align__(16) float sh_h[2][HD];   // ping-pong hidden state

    // Per-gate activation constants (branch-free core)
    const float sg = (g == 2) ? (2.0f * L2E) : (-L2E);
    const float kg = (g == 2) ? -2.0f : 1.0f;
    const float mg = (g == 2) ?  1.0f : 0.0f;

    // ---- R rows for both slots, pre-scaled by sg, packed f32x2 ----
    // RpA[m]/RpB[m] multiply h elements (2m, 2m+1).
    ull RpA[32], RpB[32];
    {
        const ull sg2 = pk2(sg, sg);
        const float4* rA = reinterpret_cast<const float4*>(
            R + (((size_t)n * NG + g) * HD + oA) * HD);
        const float4* rB = reinterpret_cast<const float4*>(
            R + (((size_t)n * NG + g) * HD + oB) * HD);
#pragma unroll
        for (int k = 0; k < 16; ++k) {
            float4 vA = rA[k];
            float4 vB = rB[k];
            RpA[2 * k]     = fmul2(pk2(vA.x, vA.y), sg2);
            RpA[2 * k + 1] = fmul2(pk2(vA.z, vA.w), sg2);
            RpB[2 * k]     = fmul2(pk2(vB.x, vB.y), sg2);
            RpB[2 * k + 1] = fmul2(pk2(vB.z, vB.w), sg2);
        }
    }
    const float bvsA = bias[((size_t)n * NG + g) * HD + oA] * sg;
    const float bvsB = bias[((size_t)n * NG + g) * HD + oB] * sg;

    // ---- Initial states (c replicated x4 over g-lanes per output) ----
    const size_t bn = (size_t)b * NHEADS + n;
    const float h0A = S0[bn * HD + oA];
    const float h0B = S0[bn * HD + oB];
    float cA = S0[(size_t)NCELLS * HD + bn * HD + oA];
    float cB = S0[(size_t)NCELLS * HD + bn * HD + oB];

    float* out_h = out;                                 // [1025][192][64]
    float* out_c = out + (size_t)(T_STEPS + 1) * OROW;  // second state plane

    if (g == 0) {
        sh_h[0][oA] = h0A;
        sh_h[0][oB] = h0B;
        out_h[bn * HD + oA] = h0A;   // t=0 h
        out_h[bn * HD + oB] = h0B;
    } else if (g == 1) {
        out_c[bn * HD + oA] = cA;    // t=0 c
        out_c[bn * HD + oB] = cB;
    }

    // ---- Wx stream pointers (slot B is +32*NG floats from slot A) ----
    const float* wxA = Wx + bn * CELLSTR + (size_t)oA * NG + g;

    __syncthreads();

    float xcA[PF], xcB[PF];
#pragma unroll
    for (int j = 0; j < PF; ++j) {
        xcA[j] = __ldcs(wxA + (size_t)j * TSTRIDE);
        xcB[j] = __ldcs(wxA + (size_t)j * TSTRIDE + 32 * NG);
    }

    int buf = 0;
    float* oh = out_h + OROW + bn * HD + oA;   // t=1 row, slot A; slot B = +32
    float* oc = out_c + OROW + bn * HD + oA;

    // One recurrence step (identical math to the 401.5us champion).
    // The only ordering change: global stores moved AFTER the barrier, so the
    // inter-warp critical path ends at the h STS.
#define STEP_BODY(XA, XB)                                                      \
    {                                                                          \
        const float xbA = fmaf((XA), sg, bvsA);                                \
        const float xbB = fmaf((XB), sg, bvsB);                                \
        ull accA[4], accB[4];                                                  \
        accA[0] = pk2(xbA, 0.0f);                                              \
        accB[0] = pk2(xbB, 0.0f);                                              \
        accA[1] = 0ULL; accA[2] = 0ULL; accA[3] = 0ULL;                        \
        accB[1] = 0ULL; accB[2] = 0ULL; accB[3] = 0ULL;                        \
        const ulonglong2* hb = reinterpret_cast<const ulonglong2*>(sh_h[buf]); \
        _Pragma("unroll")                                                      \
        for (int k = 0; k < 16; ++k) {                                         \
            ulonglong2 t2 = hb[k];                                             \
            ffma2(accA[(2 * k) & 3],     RpA[2 * k],     t2.x);                \
            ffma2(accA[(2 * k + 1) & 3], RpA[2 * k + 1], t2.y);                \
            ffma2(accB[(2 * k) & 3],     RpB[2 * k],     t2.x);                \
            ffma2(accB[(2 * k + 1) & 3], RpB[2 * k + 1], t2.y);                \
        }                                                                      \
        ull sa = fadd2(fadd2(accA[0], accA[1]), fadd2(accA[2], accA[3]));      \
        ull sb = fadd2(fadd2(accB[0], accB[1]), fadd2(accB[2], accB[3]));      \
        float lo, hi;                                                          \
        upk2(sa, lo, hi); const float sA = lo + hi;                            \
        upk2(sb, lo, hi); const float sB = lo + hi;                            \
        const float aA = fmaf(kg, frcp(1.0f + fex2(sA)), mg);                  \
        const float aB = fmaf(kg, frcp(1.0f + fex2(sB)), mg);                  \
        /* gate gather: direct indexed shuffles, no select network */          \
        const float giA = __shfl_sync(0xffffffffu, aA, Li);                    \
        const float gzA = __shfl_sync(0xffffffffu, aA, Lz);                    \
        const float gfA = __shfl_sync(0xffffffffu, aA, Lf);                    \
        const float goA = __shfl_sync(0xffffffffu, aA, Lo);                    \
        const float giB = __shfl_sync(0xffffffffu, aB, Li);                    \
        const float gzB = __shfl_sync(0xffffffffu, aB, Lz);                    \
        const float gfB = __shfl_sync(0xffffffffu, aB, Lf);                    \
        const float goB = __shfl_sync(0xffffffffu, aB, Lo);                    \
        cA = fmaf(gfA, cA, giA * gzA);                                         \
        cB = fmaf(gfB, cB, giB * gzB);                                         \
        const float rA2 = frcp(1.0f + fex2(cA * (2.0f * L2E)));                \
        const float rB2 = frcp(1.0f + fex2(cB * (2.0f * L2E)));                \
        const float hA = fmaf(-(goA + goA), rA2, goA);   /* goA*tanh(cA) */    \
        const float hB = fmaf(-(goB + goB), rB2, goB);                         \
        if (g == 0) {                                                          \
            sh_h[buf ^ 1][oA] = hA;   /* inter-warp path ends here */          \
            sh_h[buf ^ 1][oB] = hB;                                            \
        }                                                                      \
        __syncthreads();                                                       \
        /* global stores off the barrier-bound path */                         \
        if (g == 0) {                                                          \
            oh[0]  = hA;                                                       \
            oh[32] = hB;                                                       \
        } else if (g == 1) {                                                   \
            oc[0]  = cA;                                                       \
            oc[32] = cB;                                                       \
        }                                                                      \
        buf ^= 1;                                                              \
        oh += OROW;                                                            \
        oc += OROW;                                                            \
    }

    // ---- main loop: prefetch unconditional (no predication/selects) ----
    for (int t0 = 0; t0 < T_STEPS - PF; t0 += PF) {
        float xnA[PF], xnB[PF];
#pragma unroll
        for (int j = 0; j < PF; ++j) {
            const float* p = wxA + (size_t)(t0 + PF + j) * TSTRIDE;
            xnA[j] = __ldcs(p);
            xnB[j] = __ldcs(p + 32 * NG);
        }
#pragma unroll
        for (int j = 0; j < PF; ++j)
            STEP_BODY(xcA[j], xcB[j])
#pragma unroll
        for (int j = 0; j < PF; ++j) { xcA[j] = xnA[j]; xcB[j] = xnB[j]; }
    }
    // ---- tail: last PF steps, no prefetch ----
#pragma unroll
    for (int j = 0; j < PF; ++j)
        STEP_BODY(xcA[j], xcB[j])

#undef STEP_BODY
}

extern "C" void kernel_launch(void* const* d_in, const int* in_sizes, int n_in,
                              void* d_out, int out_size)
{
    const float* Wx   = (const float*)d_in[0];  // [1024,16,12,64,4]
    const float* S0   = (const float*)d_in[1];  // [2,16,12,64]
    const float* R    = (const float*)d_in[2];  // [12,4,64,64]
    const float* bias = (const float*)d_in[3];  // [12,4,64]
    float* out = (float*)d_out;                 // [2,1025,16,12,64]

    flashrnn_lstm_kernel<<<NCELLS, 128>>>(Wx, S0, R, bias, out);
}